// round 1
// baseline (speedup 1.0000x reference)
#include <cuda_runtime.h>

#define T_DIM 200
#define B_DIM 2048
#define I_DIM 128
#define H_DIM 128
#define K_LAB 4
#define S_TILE 16
#define XROW 20   // padded row stride (floats) for x s-tile: keeps float4 alignment, kills 16-way conflicts

// Shared memory layout (floats):
//  W1t   : 128*128      transposed w1 (W1t[i][h] = w1[h][i])
//  xst   : 128*XROW     x tile, [i][ss]
//  xlab  : K*128        x at labeled steps
//  xm    : K*128        running mean at labeled steps
//  hsum  : 4*K*128      per-warp partial h accumulators
//  cs    : K*128        c[k][h]
//  x2s   : K*128        x2_lab[k][h]
#define SM_W1T   0
#define SM_XST   (SM_W1T + I_DIM*H_DIM)
#define SM_XLAB  (SM_XST + I_DIM*XROW)
#define SM_XM    (SM_XLAB + K_LAB*I_DIM)
#define SM_HSUM  (SM_XM + K_LAB*I_DIM)
#define SM_CS    (SM_HSUM + 4*K_LAB*H_DIM)
#define SM_X2S   (SM_CS + K_LAB*H_DIM)
#define SM_TOTAL (SM_X2S + K_LAB*H_DIM)

__global__ __launch_bounds__(128)
void fused_attn_kernel(const float* __restrict__ inputs,
                       const int*   __restrict__ lengths,
                       const float* __restrict__ w0,
                       const float* __restrict__ w1_w,
                       const float* __restrict__ w1_b,
                       const float* __restrict__ w2_w,
                       const float* __restrict__ w3_w,
                       float* __restrict__ out)
{
    extern __shared__ float smem[];
    float* W1t  = smem + SM_W1T;
    float* xst  = smem + SM_XST;
    float* xlab = smem + SM_XLAB;
    float* xm   = smem + SM_XM;
    float* hsum = smem + SM_HSUM;
    float* cs   = smem + SM_CS;
    float* x2s  = smem + SM_X2S;

    const int b   = blockIdx.x;
    const int tid = threadIdx.x;
    const int len = lengths[b];
    const int start = max(len - K_LAB, 0);
    const int nk    = min(len, K_LAB);

    // ---------- Stage W1 transposed into SMEM (thread tid owns row h = tid) ----------
    {
        const float4* wrow = reinterpret_cast<const float4*>(w1_w + tid * I_DIM);
        #pragma unroll 8
        for (int i4 = 0; i4 < I_DIM / 4; i4++) {
            float4 v = wrow[i4];
            W1t[(i4*4 + 0) * H_DIM + tid] = v.x;
            W1t[(i4*4 + 1) * H_DIM + tid] = v.y;
            W1t[(i4*4 + 2) * H_DIM + tid] = v.z;
            W1t[(i4*4 + 3) * H_DIM + tid] = v.w;
        }
    }

    // ---------- Prefix sums: thread owns feature i = tid ----------
    {
        const int i = tid;
        float acc = 0.f;
        int s = 0;
        for (; s + 4 <= start; s += 4) {
            float a0 = inputs[((size_t)(s+0) * B_DIM + b) * I_DIM + i];
            float a1 = inputs[((size_t)(s+1) * B_DIM + b) * I_DIM + i];
            float a2 = inputs[((size_t)(s+2) * B_DIM + b) * I_DIM + i];
            float a3 = inputs[((size_t)(s+3) * B_DIM + b) * I_DIM + i];
            acc += a0 + a1 + a2 + a3;
        }
        for (; s < start; s++)
            acc += inputs[((size_t)s * B_DIM + b) * I_DIM + i];
        for (int k = 0; k < nk; k++) {           // labeled steps s = start+k < len
            float xv = inputs[((size_t)(start + k) * B_DIM + b) * I_DIM + i];
            acc += xv;
            xlab[k * I_DIM + i] = xv;
            xm  [k * I_DIM + i] = acc / (float)(start + k + 1);
        }
        for (int k = nk; k < K_LAB; k++) {       // keep SMEM garbage-free
            xlab[k * I_DIM + i] = 0.f;
            xm  [k * I_DIM + i] = 0.f;
        }
    }
    __syncthreads();

    // ---------- c[k][h] = x2_lab + w3 @ m  (thread tid owns h = tid) ----------
    {
        float x2l[K_LAB]  = {0.f, 0.f, 0.f, 0.f};
        float wmsl[K_LAB] = {0.f, 0.f, 0.f, 0.f};
        const float4* w2r = reinterpret_cast<const float4*>(w2_w + tid * I_DIM);
        const float4* w3r = reinterpret_cast<const float4*>(w3_w + tid * I_DIM);
        #pragma unroll 4
        for (int i4 = 0; i4 < I_DIM / 4; i4++) {
            float4 a2 = w2r[i4];
            float4 a3 = w3r[i4];
            #pragma unroll
            for (int k = 0; k < K_LAB; k++) {
                float4 xl = *reinterpret_cast<const float4*>(&xlab[k * I_DIM + i4*4]);
                float4 mm = *reinterpret_cast<const float4*>(&xm  [k * I_DIM + i4*4]);
                x2l[k]  += a2.x*xl.x + a2.y*xl.y + a2.z*xl.z + a2.w*xl.w;
                wmsl[k] += a3.x*mm.x + a3.y*mm.y + a3.z*mm.z + a3.w*mm.w;
            }
        }
        #pragma unroll
        for (int k = 0; k < K_LAB; k++) {
            cs [k * H_DIM + tid] = x2l[k] + wmsl[k];
            x2s[k * H_DIM + tid] = x2l[k];
        }
    }
    __syncthreads();

    // ---------- Register-resident constants for main loop ----------
    const int hgrp = tid & 31;        // h-group within warp
    const int sgrp = tid >> 5;        // warp id = s-group
    const int hg4  = hgrp * 4;

    float4 w0v = *reinterpret_cast<const float4*>(w0 + hg4);
    float4 b1v = *reinterpret_cast<const float4*>(w1_b + hg4);
    float w0r[4] = {w0v.x, w0v.y, w0v.z, w0v.w};
    float b1r[4] = {b1v.x, b1v.y, b1v.z, b1v.w};

    float ck[K_LAB][4];
    #pragma unroll
    for (int k = 0; k < K_LAB; k++) {
        float4 c4 = *reinterpret_cast<const float4*>(&cs[k * H_DIM + hg4]);
        ck[k][0] = c4.x; ck[k][1] = c4.y; ck[k][2] = c4.z; ck[k][3] = c4.w;
    }

    float hacc[K_LAB][4];
    #pragma unroll
    for (int k = 0; k < K_LAB; k++)
        #pragma unroll
        for (int j = 0; j < 4; j++) hacc[k][j] = 0.f;

    // ---------- Main loop over s tiles ----------
    for (int s0 = 0; s0 < len; s0 += S_TILE) {
        const int scount = min(S_TILE, len - s0);

        // stage x tile: thread tid owns i = tid, coalesced over ss
        #pragma unroll
        for (int ss = 0; ss < S_TILE; ss++) {
            float v = 0.f;
            if (ss < scount)
                v = inputs[((size_t)(s0 + ss) * B_DIM + b) * I_DIM + tid];
            xst[tid * XROW + ss] = v;
        }
        __syncthreads();

        // GEMV: x1[4s][4h] for this warp's s-group
        float x1a[4][4];
        #pragma unroll
        for (int sj = 0; sj < 4; sj++)
            #pragma unroll
            for (int j = 0; j < 4; j++) x1a[sj][j] = 0.f;

        #pragma unroll 4
        for (int i = 0; i < I_DIM; i++) {
            float4 wv = *reinterpret_cast<const float4*>(&W1t[i * H_DIM + hg4]);
            float4 xv = *reinterpret_cast<const float4*>(&xst[i * XROW + sgrp * 4]);
            x1a[0][0] += xv.x*wv.x; x1a[0][1] += xv.x*wv.y; x1a[0][2] += xv.x*wv.z; x1a[0][3] += xv.x*wv.w;
            x1a[1][0] += xv.y*wv.x; x1a[1][1] += xv.y*wv.y; x1a[1][2] += xv.y*wv.z; x1a[1][3] += xv.y*wv.w;
            x1a[2][0] += xv.z*wv.x; x1a[2][1] += xv.z*wv.y; x1a[2][2] += xv.z*wv.z; x1a[2][3] += xv.z*wv.w;
            x1a[3][0] += xv.w*wv.x; x1a[3][1] += xv.w*wv.y; x1a[3][2] += xv.w*wv.z; x1a[3][3] += xv.w*wv.w;
        }
        // add bias: x1a now = x1 (with bias)
        #pragma unroll
        for (int sj = 0; sj < 4; sj++)
            #pragma unroll
            for (int j = 0; j < 4; j++) x1a[sj][j] += b1r[j];

        // attention for this warp's 4 s-values
        const int sbase = s0 + sgrp * 4;
        #pragma unroll
        for (int k = 0; k < K_LAB; k++) {
            if (k >= nk) break;                 // uniform across block
            const int tk = start + k;           // t_lab[k]
            if (sbase > tk) continue;           // uniform across warp
            #pragma unroll
            for (int sj = 0; sj < 4; sj++) {
                const int s = sbase + sj;
                if (s > tk) break;              // uniform across warp (s <= tk => s < len)
                float p = 0.f;
                #pragma unroll
                for (int j = 0; j < 4; j++) {
                    float z = x1a[sj][j] + ck[k][j];
                    float sg = __fdividef(1.f, 1.f + __expf(-z));
                    p += w0r[j] * sg;
                }
                // full-warp butterfly reduce over 128 h (32 lanes x 4 h)
                #pragma unroll
                for (int off = 16; off; off >>= 1)
                    p += __shfl_xor_sync(0xffffffffu, p, off);
                #pragma unroll
                for (int j = 0; j < 4; j++)
                    hacc[k][j] += p * x1a[sj][j];
            }
        }
        __syncthreads();   // before next tile overwrites xst
    }

    // ---------- Cross-warp combine + epilogue ----------
    #pragma unroll
    for (int k = 0; k < K_LAB; k++)
        #pragma unroll
        for (int j = 0; j < 4; j++)
            hsum[(sgrp * K_LAB + k) * H_DIM + hg4 + j] = hacc[k][j];
    __syncthreads();

    #pragma unroll
    for (int k = 0; k < K_LAB; k++) {
        float v = 0.f;
        if (k < nk) {
            v = hsum[(0 * K_LAB + k) * H_DIM + tid]
              + hsum[(1 * K_LAB + k) * H_DIM + tid]
              + hsum[(2 * K_LAB + k) * H_DIM + tid]
              + hsum[(3 * K_LAB + k) * H_DIM + tid]
              + x2s[k * H_DIM + tid];
        }
        out[((size_t)b * K_LAB + k) * H_DIM + tid] = v;   // zeros for invalid k (buffer is poisoned)
    }
}

extern "C" void kernel_launch(void* const* d_in, const int* in_sizes, int n_in,
                              void* d_out, int out_size)
{
    // input order: inputs, lengths, [label_len], w0, w1_w, w1_b, w2_w, w3_w
    const int base = (n_in >= 8) ? 3 : 2;   // tolerate scalar label_len present or dropped
    const float* inputs = (const float*)d_in[0];
    const int*   lengths = (const int*)d_in[1];
    const float* w0   = (const float*)d_in[base + 0];
    const float* w1_w = (const float*)d_in[base + 1];
    const float* w1_b = (const float*)d_in[base + 2];
    const float* w2_w = (const float*)d_in[base + 3];
    const float* w3_w = (const float*)d_in[base + 4];
    float* out = (float*)d_out;

    const size_t smem_bytes = (size_t)SM_TOTAL * sizeof(float);
    cudaFuncSetAttribute(fused_attn_kernel,
                         cudaFuncAttributeMaxDynamicSharedMemorySize,
                         (int)smem_bytes);
    fused_attn_kernel<<<B_DIM, 128, smem_bytes>>>(inputs, lengths, w0, w1_w, w1_b,
                                                  w2_w, w3_w, out);
}